// round 16
// baseline (speedup 1.0000x reference)
#include <cuda_runtime.h>
#include <cuda_fp16.h>
#include <cstdint>
#include <math.h>

#define NTOK 16384
#define DIM  1024
#define NE   8
#define CAP  2560          // int(1.25 * 16384 / 8)
#define BK   64
#define NCH  (DIM / BK)    // 16
#define BH_OFF  32768      // A tile 256 rows x 128B
#define STAGE_B 49152      // + B tile 128 rows x 128B
#define NSTG 4
#define SMEM_DYN (1024 + NSTG * STAGE_B)   // 197632
#define TX_BYTES 49152
#define TILES_PER_E 80     // 10 m-tiles x 8 n-tiles
#define G1_ITEMS (NE * TILES_PER_E)     // 640
#define TOTAL_ITEMS (2 * G1_ITEMS)      // 1280
#define GRID_PERSIST 152
#define WN4  (NE * DIM * DIM / 4)       // float4 count per W tensor

// ---------------- device scratch (no allocation allowed) -------------------
// chunk-major slabs: [e*16 + c][row][64 fp16], rows pre-swizzled (SW128)
__device__ int      g_top[NTOK * 2];
__device__ float    g_gate[NTOK * 2];
__device__ int      g_slot[NTOK * 2];
__device__ int      g_row_token[NE * CAP];
__device__ float    g_row_gate[NE * CAP];
__device__ int      g_load[NE];
__device__ int      g_next;
__device__ int      g_done[NE];
__device__ uint16_t g_xh[(size_t)NTOK * DIM];          // x fp16, token-major
__device__ uint16_t g_Xg[(size_t)NE * CAP * DIM];      // gathered x, chunk-major
__device__ uint16_t g_w1h[(size_t)NE * DIM * DIM];     // W1 fp16, chunk-major
__device__ uint16_t g_w2h[(size_t)NE * DIM * DIM];     // W2 fp16, chunk-major
__device__ uint16_t g_Hh[(size_t)NE * CAP * DIM];      // hidden fp16, chunk-major
__device__ uint16_t g_Oh[(size_t)NE * CAP * DIM];      // gated out fp16, slot-major

// ---------------- helpers ---------------------------------------------------
__device__ __forceinline__ uint32_t smem_u32(const void* p) {
    uint32_t a;
    asm("{ .reg .u64 t; cvta.to.shared.u64 t, %1; cvt.u32.u64 %0, t; }"
        : "=r"(a) : "l"(p));
    return a;
}
__device__ __forceinline__ void cpbulk(uint32_t dst, const void* src,
                                       uint32_t bytes, uint32_t mbar) {
    asm volatile(
        "cp.async.bulk.shared::cluster.global.mbarrier::complete_tx::bytes "
        "[%0], [%1], %2, [%3];"
        :: "r"(dst), "l"(src), "r"(bytes), "r"(mbar) : "memory");
}
#define MBARRIER_INIT(mb, n) \
    asm volatile("mbarrier.init.shared.b64 [%0], %1;" \
                 :: "r"((uint32_t)(mb)), "r"((uint32_t)(n)) : "memory")
#define MBARRIER_EXPECT_TX(mb, tx) \
    asm volatile("mbarrier.arrive.expect_tx.shared.b64 _, [%0], %1;" \
                 :: "r"((uint32_t)(mb)), "r"((uint32_t)(tx)) : "memory")
#define FENCE_PROXY_ASYNC() \
    asm volatile("fence.proxy.async.shared::cta;" ::: "memory")
#define MBARRIER_WAIT_PARITY(mb, par) do {                                      \
    uint32_t _mb = (uint32_t)(mb); uint32_t _p = (uint32_t)(par); uint32_t _d;  \
    asm volatile("{ .reg .pred p; mbarrier.try_wait.parity.acquire.cta.shared::cta.b64 p, [%1], %2;" \
                 " selp.b32 %0, 1, 0, p; }" : "=r"(_d) : "r"(_mb), "r"(_p) : "memory"); \
    if (!_d) {                                                                   \
        asm volatile("{ .reg .pred P1; WL_%=:"                                   \
                     " mbarrier.try_wait.parity.acquire.cta.shared::cta.b64 P1, [%0], %1, 0x989680;" \
                     " @P1 bra.uni WD_%=; bra.uni WL_%=; WD_%=: }"               \
                     :: "r"(_mb), "r"(_p) : "memory");                           \
    }                                                                            \
} while (0)

__device__ __forceinline__ void ldsm4(uint32_t* r, uint32_t addr) {
    asm volatile("ldmatrix.sync.aligned.m8n8.x4.shared.b16 {%0,%1,%2,%3}, [%4];"
                 : "=r"(r[0]), "=r"(r[1]), "=r"(r[2]), "=r"(r[3]) : "r"(addr));
}
__device__ __forceinline__ void mma_f16(float* d, const uint32_t* a,
                                        const uint32_t* b) {
    asm volatile(
        "mma.sync.aligned.m16n8k16.row.col.f32.f16.f16.f32 "
        "{%0,%1,%2,%3}, {%4,%5,%6,%7}, {%8,%9}, {%0,%1,%2,%3};"
        : "+f"(d[0]), "+f"(d[1]), "+f"(d[2]), "+f"(d[3])
        : "r"(a[0]), "r"(a[1]), "r"(a[2]), "r"(a[3]), "r"(b[0]), "r"(b[1]));
}
__device__ __forceinline__ uint32_t cvt2h(float a, float b) {
    __half2 h = __floats2half2_rn(a, b);
    return *(uint32_t*)&h;
}
__device__ __forceinline__ int ld_acq(const int* p) {
    int v;
    asm volatile("ld.acquire.gpu.global.b32 %0, [%1];" : "=r"(v) : "l"(p));
    return v;
}

// ---------------- W convert: fp32 -> fp16, chunk-major + swizzled ----------
__global__ void __launch_bounds__(256)
cvtw_kernel(const float4* __restrict__ W1, const float4* __restrict__ W2) {
    int i = blockIdx.x * 256 + threadIdx.x;
    const float4* src;
    uint16_t* dstb;
    if (i < WN4) { src = W1; dstb = g_w1h; }
    else         { src = W2; dstb = g_w2h; i -= WN4; }
    float4 v = __ldg(src + i);
    const int lin = i * 4;                    // element index
    const int e = lin >> 20;
    const int rem = lin & 1048575;
    const int n = rem >> 10;
    const int k = rem & 1023;
    const int c = k >> 6;
    const int q = (k & 63) >> 3;
    const size_t rowbyte = ((size_t)((e * 16 + c) * 1024 + n)) << 7;
    const uint32_t off = (uint32_t)(((q ^ (n & 7)) << 4) + (k & 7) * 2);
    *(uint2*)((char*)dstb + rowbyte + off) =
        make_uint2(cvt2h(v.x, v.y), cvt2h(v.z, v.w));
}

// ---------------- router + x->fp16, 4 tokens/warp --------------------------
__global__ void __launch_bounds__(256)
router_kernel(const float* __restrict__ x, const float* __restrict__ Wr,
              const float* __restrict__ br) {
    const int tid = threadIdx.x;
    const int lane = tid & 31, wid = tid >> 5;
    const int tb = (blockIdx.x * 8 + wid) * 4;
    const float4* xr[4];
    uint2* xo[4];
#pragma unroll
    for (int t = 0; t < 4; t++) {
        xr[t] = (const float4*)(x + (size_t)(tb + t) * DIM);
        xo[t] = (uint2*)(g_xh + (size_t)(tb + t) * DIM);
    }
    float acc[4][NE];
#pragma unroll
    for (int t = 0; t < 4; t++)
#pragma unroll
        for (int e = 0; e < NE; e++) acc[t][e] = 0.f;
#pragma unroll
    for (int i = 0; i < 8; i++) {
        const int d4 = lane + i * 32;
        float4 xv[4];
#pragma unroll
        for (int t = 0; t < 4; t++) {
            xv[t] = __ldg(xr[t] + d4);
            xo[t][d4] = make_uint2(cvt2h(xv[t].x, xv[t].y), cvt2h(xv[t].z, xv[t].w));
        }
#pragma unroll
        for (int e = 0; e < NE; e++) {
            const float4 w = __ldg((const float4*)(Wr + e * DIM) + d4);
#pragma unroll
            for (int t = 0; t < 4; t++)
                acc[t][e] += xv[t].x * w.x + xv[t].y * w.y
                           + xv[t].z * w.z + xv[t].w * w.w;
        }
    }
#pragma unroll
    for (int t = 0; t < 4; t++)
#pragma unroll
        for (int e = 0; e < NE; e++)
#pragma unroll
            for (int o = 16; o; o >>= 1)
                acc[t][e] += __shfl_xor_sync(0xffffffffu, acc[t][e], o);
    if (lane == 0) {
#pragma unroll
        for (int t = 0; t < 4; t++) {
            const int token = tb + t;
            float l[NE];
#pragma unroll
            for (int e = 0; e < NE; e++) l[e] = acc[t][e] + br[e];
            float v1 = -3.4e38f; int i1 = 0;
#pragma unroll
            for (int e = 0; e < NE; e++) if (l[e] > v1) { v1 = l[e]; i1 = e; }
            float v2 = -3.4e38f; int i2 = 0;
#pragma unroll
            for (int e = 0; e < NE; e++) if (e != i1 && l[e] > v2) { v2 = l[e]; i2 = e; }
            float ex = expf(v2 - v1);
            float inv = 1.f / (1.f + ex);
            g_top[2 * token]      = i1;
            g_top[2 * token + 1]  = i2;
            g_gate[2 * token]     = inv;
            g_gate[2 * token + 1] = ex * inv;
        }
    }
}

// ---------------- dispatch scan: 16 tokens/thread, one block scan ----------
__global__ void __launch_bounds__(1024)
scan_kernel() {
    const int e = blockIdx.x;
    const int tid = threadIdx.x;
    const int lane = tid & 31, wid = tid >> 5;
    __shared__ int wsum[32];
    __shared__ int stotal;

    const int base = tid * 16;
    unsigned mask = 0, which = 0;
    int cnt = 0;
#pragma unroll
    for (int j = 0; j < 16; j++) {
        const int n = base + j;
        const int t0 = g_top[2 * n], t1 = g_top[2 * n + 1];
        const bool m0 = (t0 == e), m1 = (t1 == e);
        if (m0 | m1) {
            mask |= 1u << j;
            if (!m0) which |= 1u << j;
            cnt++;
        }
    }
    int s = cnt;
#pragma unroll
    for (int o = 1; o < 32; o <<= 1) {
        int u = __shfl_up_sync(0xffffffffu, s, o);
        if (lane >= o) s += u;
    }
    if (lane == 31) wsum[wid] = s;
    const int wexcl = s - cnt;
    __syncthreads();
    if (wid == 0) {
        int v = wsum[lane];
        int ss = v;
#pragma unroll
        for (int o = 1; o < 32; o <<= 1) {
            int u = __shfl_up_sync(0xffffffffu, ss, o);
            if (lane >= o) ss += u;
        }
        wsum[lane] = ss - v;
        if (lane == 31) stotal = ss;
    }
    __syncthreads();
    int pos = wsum[wid] + wexcl;
#pragma unroll
    for (int j = 0; j < 16; j++) {
        if (mask & (1u << j)) {
            const int n = base + j;
            const int k = (which >> j) & 1;
            if (pos < CAP) {
                g_row_token[e * CAP + pos] = n;
                g_row_gate[e * CAP + pos]  = g_gate[2 * n + k];
                g_slot[2 * n + k] = pos;
            } else {
                g_slot[2 * n + k] = -1;
            }
            pos++;
        }
    }
    if (tid == 0) g_load[e] = stotal < CAP ? stotal : CAP;
}

// ---------------- gather: routed x rows -> chunk-major swizzled g_Xg -------
// one thread per (expert-slot, chunk-pair): 16 loads + 16 stores in flight
__global__ void __launch_bounds__(256)
gather_kernel() {
    const int gi = blockIdx.x * 256 + threadIdx.x;   // NE*CAP*8
    const int cp = gi & 7;                           // chunk pair
    const int slotg = gi >> 3;                       // e*CAP + slot
    const int e = slotg / CAP;
    const int slot = slotg - e * CAP;
    if (slot >= g_load[e]) return;                   // unrouted: leave garbage
    const int token = g_row_token[slotg];
    const int c0 = cp * 2;
    const uint4* s0 = (const uint4*)(g_xh + (size_t)token * DIM + c0 * 64);
    const uint4* s1 = s0 + 8;
    char* d0 = (char*)g_Xg + (((size_t)(e * 16 + c0) * CAP + slot) << 7);
    char* d1 = (char*)g_Xg + (((size_t)(e * 16 + c0 + 1) * CAP + slot) << 7);
    const int sw = slot & 7;
    uint4 v0[8], v1[8];
#pragma unroll
    for (int q = 0; q < 8; q++) { v0[q] = __ldg(s0 + q); v1[q] = __ldg(s1 + q); }
#pragma unroll
    for (int q = 0; q < 8; q++) {
        *(uint4*)(d0 + ((q ^ sw) << 4)) = v0[q];
        *(uint4*)(d1 + ((q ^ sw) << 4)) = v1[q];
    }
}

// ---------------- fused persistent GEMM: 3 bulk copies/chunk, 4 stages -----
__global__ void __launch_bounds__(256)
moe_gemm_fused(const float* __restrict__ b1, const float* __restrict__ b2) {
    extern __shared__ __align__(128) char dsm[];
    __shared__ int sidx;

    const int tid = threadIdx.x;
    const int lane = tid & 31, wid = tid >> 5;
    const int wm = wid >> 1, wn = wid & 1;     // warp tile 64x64
    const uint32_t sb = smem_u32(dsm);
    const uint32_t st0 = sb + 1024;

    if (tid == 0) {
#pragma unroll
        for (int s = 0; s < NSTG; s++) MBARRIER_INIT(sb + 8 * s, 1);
        FENCE_PROXY_ASYNC();
    }
    __syncthreads();
    int ph[NSTG] = {0, 0, 0, 0};

    const uint32_t rx = (uint32_t)(lane & 7);
    uint32_t xqa[4], xqb[4];
#pragma unroll
    for (int s = 0; s < 4; s++) {
        xqa[s] = (((uint32_t)(2 * s) + (uint32_t)(lane >> 4)) ^ rx) << 4;
        xqb[s] = (((uint32_t)(2 * s) + (uint32_t)((lane >> 3) & 1)) ^ rx) << 4;
    }
    uint32_t abase[4], bbase[4];
#pragma unroll
    for (int ms = 0; ms < 4; ms++)
        abase[ms] = (uint32_t)(wm * 64 + ms * 16 + (lane & 15)) << 7;
#pragma unroll
    for (int np = 0; np < 4; np++)
        bbase[np] = BH_OFF + ((uint32_t)(wn * 64 + np * 16 + (lane & 7)
                                        + ((lane >> 4) & 1) * 8) << 7);

    while (true) {
        if (tid == 0) sidx = atomicAdd(&g_next, 1);
        __syncthreads();
        const int idx = sidx;
        __syncthreads();
        if (idx >= TOTAL_ITEMS) return;

        const bool G2 = idx >= G1_ITEMS;
        const int t  = G2 ? idx - G1_ITEMS : idx;
        const int e  = t / TILES_PER_E;
        const int mt = (t % TILES_PER_E) >> 3;
        const int nt = t & 7;
        const int m0 = mt * 256, n0 = nt * 128;
        const int loadE = g_load[e];

        if (G2) {
            if (tid == 0)
                while (ld_acq(&g_done[e]) < TILES_PER_E) __nanosleep(64);
            __syncthreads();
        }

        if (m0 < loadE) {
            const char* Aslab = (const char*)((G2 ? g_Hh : g_Xg)
                               + (size_t)e * 16 * CAP * 64);
            const char* Bslab = (const char*)((G2 ? g_w2h : g_w1h)
                               + (size_t)e * 16 * 1024 * 64);

            auto issue = [&](int c) {    // tid0 only
                const int s = c & (NSTG - 1);
                const uint32_t st = st0 + (uint32_t)s * STAGE_B;
                const uint32_t mb = sb + 8u * (uint32_t)s;
                const char* aS = Aslab + (((size_t)c * CAP + m0) << 7);
                const char* bS = Bslab + (((size_t)c * 1024 + n0) << 7);
                cpbulk(st,          aS,         16384, mb);
                cpbulk(st + 16384,  aS + 16384, 16384, mb);
                cpbulk(st + BH_OFF, bS,         16384, mb);
            };

            float acc[4][8][4];
#pragma unroll
            for (int i = 0; i < 4; i++)
#pragma unroll
                for (int j = 0; j < 8; j++)
#pragma unroll
                    for (int k = 0; k < 4; k++) acc[i][j][k] = 0.f;

            if (tid == 0) {
#pragma unroll
                for (int c0 = 0; c0 < NSTG - 1; c0++) {
                    MBARRIER_EXPECT_TX(sb + 8u * (uint32_t)c0, TX_BYTES);
                    issue(c0);
                }
            }

#pragma unroll 1
            for (int c = 0; c < NCH; c++) {
                const int s = c & (NSTG - 1);
                MBARRIER_WAIT_PARITY(sb + 8u * (uint32_t)s, ph[s]);
                ph[s] ^= 1;
                __syncthreads();         // readers of stage (c-1)%NSTG done
                if (tid == 0 && c + NSTG - 1 < NCH) {
                    const int sn = (c + NSTG - 1) & (NSTG - 1);
                    MBARRIER_EXPECT_TX(sb + 8u * (uint32_t)sn, TX_BYTES);
                    issue(c + NSTG - 1);
                }
                const uint32_t st = st0 + (uint32_t)s * STAGE_B;
                uint32_t ah[2][16], bh[2][16];
#pragma unroll
                for (int ms = 0; ms < 4; ms++)
                    ldsm4(&ah[0][4 * ms], st + abase[ms] + xqa[0]);
#pragma unroll
                for (int np = 0; np < 4; np++)
                    ldsm4(&bh[0][4 * np], st + bbase[np] + xqb[0]);
#pragma unroll
                for (int s2 = 0; s2 < 4; s2++) {
                    const int cur = s2 & 1, nxt = cur ^ 1;
                    if (s2 < 3) {
#pragma unroll
                        for (int ms = 0; ms < 4; ms++)
                            ldsm4(&ah[nxt][4 * ms], st + abase[ms] + xqa[s2 + 1]);
#pragma unroll
                        for (int np = 0; np < 4; np++)
                            ldsm4(&bh[nxt][4 * np], st + bbase[np] + xqb[s2 + 1]);
                    }
#pragma unroll
                    for (int ms = 0; ms < 4; ms++)
#pragma unroll
                        for (int ns = 0; ns < 8; ns++)
                            mma_f16(acc[ms][ns], &ah[cur][4 * ms], &bh[cur][2 * ns]);
                }
            }

            // ---- epilogue ----
            const float* bE = (G2 ? b2 : b1) + e * DIM;
#pragma unroll
            for (int ms = 0; ms < 4; ms++) {
                const int row = m0 + wm * 64 + ms * 16 + (lane >> 2);
                float gr0 = 1.f, gr1 = 1.f;
                if (G2) {
                    gr0 = g_row_gate[e * CAP + row];
                    gr1 = g_row_gate[e * CAP + row + 8];
                }
#pragma unroll
                for (int ns = 0; ns < 8; ns++) {
                    const int col = n0 + wn * 64 + ns * 8 + 2 * (lane & 3);
                    const float2 bv = *(const float2*)(bE + col);
                    float2 v0, v1;
                    v0.x = acc[ms][ns][0] + bv.x; v0.y = acc[ms][ns][1] + bv.y;
                    v1.x = acc[ms][ns][2] + bv.x; v1.y = acc[ms][ns][3] + bv.y;
                    if (G2) {
                        const size_t i0 = ((size_t)e * CAP + row) * DIM + col;
                        *(uint32_t*)(g_Oh + i0) = cvt2h(v0.x * gr0, v0.y * gr0);
                        *(uint32_t*)(g_Oh + i0 + 8 * DIM) = cvt2h(v1.x * gr1, v1.y * gr1);
                    } else {
                        v0.x = v0.x > 0.f ? v0.x : 0.f; v0.y = v0.y > 0.f ? v0.y : 0.f;
                        v1.x = v1.x > 0.f ? v1.x : 0.f; v1.y = v1.y > 0.f ? v1.y : 0.f;
                        const int cs = (n0 >> 6) + wn;
                        char* hr = (char*)g_Hh
                                 + (((size_t)(e * 16 + cs) * CAP + row) << 7)
                                 + (((ns ^ (row & 7)) << 4) + 4 * (lane & 3));
                        *(uint32_t*)hr = cvt2h(v0.x, v0.y);
                        *(uint32_t*)(hr + 8 * 128) = cvt2h(v1.x, v1.y);
                    }
                }
            }
        }

        __syncthreads();                 // all stores done before release
        if (!G2 && tid == 0) {
            __threadfence();
            atomicAdd(&g_done[e], 1);
        }
    }
}

// ---------------- combine (+stats block): out[t] = sum_k Oh[e_k, slot_k] ---
__global__ void combine_kernel(float* __restrict__ out) {
    if (blockIdx.x == NTOK / 8) {
        if (threadIdx.x == 0) {
            float l[NE], s = 0.f;
#pragma unroll
            for (int e = 0; e < NE; e++) { l[e] = (float)g_load[e]; s += l[e]; }
            float inv = 1.f / (s + 1e-8f);
            float loss = 0.f;
#pragma unroll
            for (int e = 0; e < NE; e++) {
                float d = l[e] * inv;
                out[(size_t)NTOK * DIM + 1 + e] = d;
                loss -= d * logf(d + 1e-8f);
            }
            out[(size_t)NTOK * DIM] = loss;
        }
        return;
    }
    int t = blockIdx.x * 8 + (threadIdx.x >> 5);
    int lane = threadIdx.x & 31;
    float acc[4][8];
#pragma unroll
    for (int i = 0; i < 4; i++)
#pragma unroll
        for (int j = 0; j < 8; j++) acc[i][j] = 0.f;
#pragma unroll
    for (int k = 0; k < 2; k++) {
        int s = g_slot[2 * t + k];
        if (s >= 0) {
            int e = g_top[2 * t + k];
            const uint4* p = (const uint4*)(g_Oh + ((size_t)e * CAP + s) * DIM);
#pragma unroll
            for (int i = 0; i < 4; i++) {
                uint4 v = __ldg(p + lane + i * 32);
                const uint32_t w[4] = {v.x, v.y, v.z, v.w};
#pragma unroll
                for (int j = 0; j < 4; j++) {
                    float2 f = __half22float2(*(const __half2*)&w[j]);
                    acc[i][2 * j]     += f.x;
                    acc[i][2 * j + 1] += f.y;
                }
            }
        }
    }
    float4* o = (float4*)(out + (size_t)t * DIM);
#pragma unroll
    for (int i = 0; i < 4; i++) {
        o[2 * (lane + i * 32)]     = make_float4(acc[i][0], acc[i][1], acc[i][2], acc[i][3]);
        o[2 * (lane + i * 32) + 1] = make_float4(acc[i][4], acc[i][5], acc[i][6], acc[i][7]);
    }
}

// ---------------- launch ----------------------------------------------------
extern "C" void kernel_launch(void* const* d_in, const int* in_sizes, int n_in,
                              void* d_out, int out_size) {
    const float* x  = (const float*)d_in[0];
    const float* Wr = (const float*)d_in[1];
    const float* br = (const float*)d_in[2];
    const float* W1 = (const float*)d_in[3];
    const float* b1 = (const float*)d_in[4];
    const float* W2 = (const float*)d_in[5];
    const float* b2 = (const float*)d_in[6];
    float* out = (float*)d_out;

    cudaFuncSetAttribute(moe_gemm_fused,
                         cudaFuncAttributeMaxDynamicSharedMemorySize, SMEM_DYN);

    void *pnext, *pdone;
    cudaGetSymbolAddress(&pnext, g_next);
    cudaGetSymbolAddress(&pdone, g_done);
    cudaMemsetAsync(pnext, 0, sizeof(int), 0);
    cudaMemsetAsync(pdone, 0, NE * sizeof(int), 0);

    cvtw_kernel<<<2 * WN4 / 256, 256>>>((const float4*)W1, (const float4*)W2);
    router_kernel<<<NTOK / 32, 256>>>(x, Wr, br);
    scan_kernel<<<NE, 1024>>>();
    gather_kernel<<<NE * CAP * 8 / 256, 256>>>();
    moe_gemm_fused<<<GRID_PERSIST, 256, SMEM_DYN>>>(b1, b2);
    combine_kernel<<<NTOK / 8 + 1, 256>>>(out);
}

// round 17
// speedup vs baseline: 1.0339x; 1.0339x over previous
#include <cuda_runtime.h>
#include <cuda_fp16.h>
#include <cstdint>
#include <math.h>

#define NTOK 16384
#define DIM  1024
#define NE   8
#define CAP  2560          // int(1.25 * 16384 / 8)
#define BK   64
#define NCH  (DIM / BK)    // 16
#define BH_OFF  32768      // A tile 256 rows x 128B
#define STAGE_B 49152      // + B tile 128 rows x 128B
#define SMEM_DYN (1024 + 3 * STAGE_B)   // 148480
#define TX_BYTES 49152
#define TILES_PER_E 80     // 10 m-tiles x 8 n-tiles
#define G1_ITEMS (NE * TILES_PER_E)     // 640
#define TOTAL_ITEMS (2 * G1_ITEMS)      // 1280
#define GRID_PERSIST 152
#define WN4  (NE * DIM * DIM / 4)       // float4 count per W tensor

// ---------------- device scratch (no allocation allowed) -------------------
// chunk-major slabs: [e*16 + c][row][64 fp16], rows pre-swizzled (SW128)
__device__ int      g_top[NTOK * 2];
__device__ float    g_gate[NTOK * 2];
__device__ int      g_slot[NTOK * 2];
__device__ int      g_row_token[NE * CAP];
__device__ float    g_row_gate[NE * CAP];
__device__ int      g_load[NE];
__device__ int      g_next;
__device__ int      g_done[NE];
__device__ uint16_t g_xh[(size_t)NTOK * DIM];          // x fp16, token-major
__device__ uint16_t g_Xg[(size_t)NE * CAP * DIM];      // gathered x, chunk-major
__device__ uint16_t g_w1h[(size_t)NE * DIM * DIM];     // W1 fp16, chunk-major
__device__ uint16_t g_w2h[(size_t)NE * DIM * DIM];     // W2 fp16, chunk-major
__device__ uint16_t g_Hh[(size_t)NE * CAP * DIM];      // hidden fp16, chunk-major
// gated out fp16: [nt 0..7][e*CAP+slot][128 fp16], 128B-halves unit-swizzled
__device__ uint16_t g_Oh[(size_t)NE * CAP * DIM];

// ---------------- helpers ---------------------------------------------------
__device__ __forceinline__ uint32_t smem_u32(const void* p) {
    uint32_t a;
    asm("{ .reg .u64 t; cvta.to.shared.u64 t, %1; cvt.u32.u64 %0, t; }"
        : "=r"(a) : "l"(p));
    return a;
}
__device__ __forceinline__ void cpbulk(uint32_t dst, const void* src,
                                       uint32_t bytes, uint32_t mbar) {
    asm volatile(
        "cp.async.bulk.shared::cluster.global.mbarrier::complete_tx::bytes "
        "[%0], [%1], %2, [%3];"
        :: "r"(dst), "l"(src), "r"(bytes), "r"(mbar) : "memory");
}
__device__ __forceinline__ void bulkst(void* gdst, uint32_t ssrc,
                                       uint32_t bytes) {
    asm volatile("cp.async.bulk.global.shared::cta.bulk_group [%0], [%1], %2;"
                 :: "l"(gdst), "r"(ssrc), "r"(bytes) : "memory");
}
#define CPB_COMMIT() asm volatile("cp.async.bulk.commit_group;" ::: "memory")
#define CPB_WAIT0()  asm volatile("cp.async.bulk.wait_group 0;" ::: "memory")
#define MBARRIER_INIT(mb, n) \
    asm volatile("mbarrier.init.shared.b64 [%0], %1;" \
                 :: "r"((uint32_t)(mb)), "r"((uint32_t)(n)) : "memory")
#define MBARRIER_EXPECT_TX(mb, tx) \
    asm volatile("mbarrier.arrive.expect_tx.shared.b64 _, [%0], %1;" \
                 :: "r"((uint32_t)(mb)), "r"((uint32_t)(tx)) : "memory")
#define FENCE_PROXY_ASYNC() \
    asm volatile("fence.proxy.async.shared::cta;" ::: "memory")
#define MBARRIER_WAIT_PARITY(mb, par) do {                                      \
    uint32_t _mb = (uint32_t)(mb); uint32_t _p = (uint32_t)(par); uint32_t _d;  \
    asm volatile("{ .reg .pred p; mbarrier.try_wait.parity.acquire.cta.shared::cta.b64 p, [%1], %2;" \
                 " selp.b32 %0, 1, 0, p; }" : "=r"(_d) : "r"(_mb), "r"(_p) : "memory"); \
    if (!_d) {                                                                   \
        asm volatile("{ .reg .pred P1; WL_%=:"                                   \
                     " mbarrier.try_wait.parity.acquire.cta.shared::cta.b64 P1, [%0], %1, 0x989680;" \
                     " @P1 bra.uni WD_%=; bra.uni WL_%=; WD_%=: }"               \
                     :: "r"(_mb), "r"(_p) : "memory");                           \
    }                                                                            \
} while (0)

__device__ __forceinline__ void ldsm4(uint32_t* r, uint32_t addr) {
    asm volatile("ldmatrix.sync.aligned.m8n8.x4.shared.b16 {%0,%1,%2,%3}, [%4];"
                 : "=r"(r[0]), "=r"(r[1]), "=r"(r[2]), "=r"(r[3]) : "r"(addr));
}
__device__ __forceinline__ void mma_f16(float* d, const uint32_t* a,
                                        const uint32_t* b) {
    asm volatile(
        "mma.sync.aligned.m16n8k16.row.col.f32.f16.f16.f32 "
        "{%0,%1,%2,%3}, {%4,%5,%6,%7}, {%8,%9}, {%0,%1,%2,%3};"
        : "+f"(d[0]), "+f"(d[1]), "+f"(d[2]), "+f"(d[3])
        : "r"(a[0]), "r"(a[1]), "r"(a[2]), "r"(a[3]), "r"(b[0]), "r"(b[1]));
}
__device__ __forceinline__ uint32_t cvt2h(float a, float b) {
    __half2 h = __floats2half2_rn(a, b);
    return *(uint32_t*)&h;
}
__device__ __forceinline__ int ld_acq(const int* p) {
    int v;
    asm volatile("ld.acquire.gpu.global.b32 %0, [%1];" : "=r"(v) : "l"(p));
    return v;
}

// ---------------- W convert: fp32 -> fp16, chunk-major + swizzled ----------
__global__ void __launch_bounds__(256)
cvtw_kernel(const float4* __restrict__ W1, const float4* __restrict__ W2) {
    int i = blockIdx.x * 256 + threadIdx.x;
    const float4* src;
    uint16_t* dstb;
    if (i < WN4) { src = W1; dstb = g_w1h; }
    else         { src = W2; dstb = g_w2h; i -= WN4; }
    float4 v = __ldg(src + i);
    const int lin = i * 4;                    // element index
    const int e = lin >> 20;
    const int rem = lin & 1048575;
    const int n = rem >> 10;
    const int k = rem & 1023;
    const int c = k >> 6;
    const int q = (k & 63) >> 3;
    const size_t rowbyte = ((size_t)((e * 16 + c) * 1024 + n)) << 7;
    const uint32_t off = (uint32_t)(((q ^ (n & 7)) << 4) + (k & 7) * 2);
    *(uint2*)((char*)dstb + rowbyte + off) =
        make_uint2(cvt2h(v.x, v.y), cvt2h(v.z, v.w));
}

// ---------------- router + x->fp16, 4 tokens/warp --------------------------
__global__ void __launch_bounds__(256)
router_kernel(const float* __restrict__ x, const float* __restrict__ Wr,
              const float* __restrict__ br) {
    const int tid = threadIdx.x;
    const int lane = tid & 31, wid = tid >> 5;
    const int tb = (blockIdx.x * 8 + wid) * 4;
    const float4* xr[4];
    uint2* xo[4];
#pragma unroll
    for (int t = 0; t < 4; t++) {
        xr[t] = (const float4*)(x + (size_t)(tb + t) * DIM);
        xo[t] = (uint2*)(g_xh + (size_t)(tb + t) * DIM);
    }
    float acc[4][NE];
#pragma unroll
    for (int t = 0; t < 4; t++)
#pragma unroll
        for (int e = 0; e < NE; e++) acc[t][e] = 0.f;
#pragma unroll
    for (int i = 0; i < 8; i++) {
        const int d4 = lane + i * 32;
        float4 xv[4];
#pragma unroll
        for (int t = 0; t < 4; t++) {
            xv[t] = __ldg(xr[t] + d4);
            xo[t][d4] = make_uint2(cvt2h(xv[t].x, xv[t].y), cvt2h(xv[t].z, xv[t].w));
        }
#pragma unroll
        for (int e = 0; e < NE; e++) {
            const float4 w = __ldg((const float4*)(Wr + e * DIM) + d4);
#pragma unroll
            for (int t = 0; t < 4; t++)
                acc[t][e] += xv[t].x * w.x + xv[t].y * w.y
                           + xv[t].z * w.z + xv[t].w * w.w;
        }
    }
#pragma unroll
    for (int t = 0; t < 4; t++)
#pragma unroll
        for (int e = 0; e < NE; e++)
#pragma unroll
            for (int o = 16; o; o >>= 1)
                acc[t][e] += __shfl_xor_sync(0xffffffffu, acc[t][e], o);
    if (lane == 0) {
#pragma unroll
        for (int t = 0; t < 4; t++) {
            const int token = tb + t;
            float l[NE];
#pragma unroll
            for (int e = 0; e < NE; e++) l[e] = acc[t][e] + br[e];
            float v1 = -3.4e38f; int i1 = 0;
#pragma unroll
            for (int e = 0; e < NE; e++) if (l[e] > v1) { v1 = l[e]; i1 = e; }
            float v2 = -3.4e38f; int i2 = 0;
#pragma unroll
            for (int e = 0; e < NE; e++) if (e != i1 && l[e] > v2) { v2 = l[e]; i2 = e; }
            float ex = expf(v2 - v1);
            float inv = 1.f / (1.f + ex);
            g_top[2 * token]      = i1;
            g_top[2 * token + 1]  = i2;
            g_gate[2 * token]     = inv;
            g_gate[2 * token + 1] = ex * inv;
        }
    }
}

// ---------------- dispatch scan: 16 tokens/thread, one block scan ----------
__global__ void __launch_bounds__(1024)
scan_kernel() {
    const int e = blockIdx.x;
    const int tid = threadIdx.x;
    const int lane = tid & 31, wid = tid >> 5;
    __shared__ int wsum[32];
    __shared__ int stotal;

    const int base = tid * 16;
    unsigned mask = 0, which = 0;
    int cnt = 0;
#pragma unroll
    for (int j = 0; j < 16; j++) {
        const int n = base + j;
        const int t0 = g_top[2 * n], t1 = g_top[2 * n + 1];
        const bool m0 = (t0 == e), m1 = (t1 == e);
        if (m0 | m1) {
            mask |= 1u << j;
            if (!m0) which |= 1u << j;
            cnt++;
        }
    }
    int s = cnt;
#pragma unroll
    for (int o = 1; o < 32; o <<= 1) {
        int u = __shfl_up_sync(0xffffffffu, s, o);
        if (lane >= o) s += u;
    }
    if (lane == 31) wsum[wid] = s;
    const int wexcl = s - cnt;
    __syncthreads();
    if (wid == 0) {
        int v = wsum[lane];
        int ss = v;
#pragma unroll
        for (int o = 1; o < 32; o <<= 1) {
            int u = __shfl_up_sync(0xffffffffu, ss, o);
            if (lane >= o) ss += u;
        }
        wsum[lane] = ss - v;
        if (lane == 31) stotal = ss;
    }
    __syncthreads();
    int pos = wsum[wid] + wexcl;
#pragma unroll
    for (int j = 0; j < 16; j++) {
        if (mask & (1u << j)) {
            const int n = base + j;
            const int k = (which >> j) & 1;
            if (pos < CAP) {
                g_row_token[e * CAP + pos] = n;
                g_row_gate[e * CAP + pos]  = g_gate[2 * n + k];
                g_slot[2 * n + k] = pos;
            } else {
                g_slot[2 * n + k] = -1;
            }
            pos++;
        }
    }
    if (tid == 0) g_load[e] = stotal < CAP ? stotal : CAP;
}

// ---------------- gather: routed x rows -> chunk-major swizzled g_Xg -------
// one thread per (expert-slot, chunk): copies 128B with SW128 swizzle
__global__ void __launch_bounds__(256)
gather_kernel() {
    const int gi = blockIdx.x * 256 + threadIdx.x;   // NE*CAP*16
    const int c = gi & 15;
    const int slotg = gi >> 4;                       // e*CAP + slot
    const int e = slotg / CAP;
    const int slot = slotg - e * CAP;
    if (slot >= g_load[e]) return;                   // unrouted: leave garbage
    const int token = g_row_token[slotg];
    const uint4* src = (const uint4*)(g_xh + (size_t)token * DIM + c * 64);
    char* dst = (char*)g_Xg + (((size_t)(e * 16 + c) * CAP + slot) << 7);
    const int sw = slot & 7;
#pragma unroll
    for (int q = 0; q < 8; q++)
        *(uint4*)(dst + ((q ^ sw) << 4)) = __ldg(src + q);
}

// ---------------- fused persistent GEMM: 3 bulk copies per chunk -----------
__global__ void __launch_bounds__(256)
moe_gemm_fused(const float* __restrict__ b1, const float* __restrict__ b2) {
    extern __shared__ __align__(128) char dsm[];
    __shared__ int sidx;

    const int tid = threadIdx.x;
    const int lane = tid & 31, wid = tid >> 5;
    const int wm = wid >> 1, wn = wid & 1;     // warp tile 64x64
    const uint32_t sb = smem_u32(dsm);
    const uint32_t st0 = sb + 1024;

    if (tid == 0) {
        MBARRIER_INIT(sb + 0, 1);
        MBARRIER_INIT(sb + 8, 1);
        MBARRIER_INIT(sb + 16, 1);
        FENCE_PROXY_ASYNC();
    }
    __syncthreads();
    int ph[3] = {0, 0, 0};

    const uint32_t rx = (uint32_t)(lane & 7);
    uint32_t xqa[4], xqb[4];
#pragma unroll
    for (int s = 0; s < 4; s++) {
        xqa[s] = (((uint32_t)(2 * s) + (uint32_t)(lane >> 4)) ^ rx) << 4;
        xqb[s] = (((uint32_t)(2 * s) + (uint32_t)((lane >> 3) & 1)) ^ rx) << 4;
    }
    uint32_t abase[4], bbase[4];
#pragma unroll
    for (int ms = 0; ms < 4; ms++)
        abase[ms] = (uint32_t)(wm * 64 + ms * 16 + (lane & 15)) << 7;
#pragma unroll
    for (int np = 0; np < 4; np++)
        bbase[np] = BH_OFF + ((uint32_t)(wn * 64 + np * 16 + (lane & 7)
                                        + ((lane >> 4) & 1) * 8) << 7);

    while (true) {
        if (tid == 0) sidx = atomicAdd(&g_next, 1);
        __syncthreads();
        const int idx = sidx;
        __syncthreads();
        if (idx >= TOTAL_ITEMS) return;

        const bool G2 = idx >= G1_ITEMS;
        const int t  = G2 ? idx - G1_ITEMS : idx;
        const int e  = t / TILES_PER_E;
        const int mt = (t % TILES_PER_E) >> 3;
        const int nt = t & 7;
        const int m0 = mt * 256, n0 = nt * 128;
        const int loadE = g_load[e];

        if (G2) {
            if (tid == 0)
                while (ld_acq(&g_done[e]) < TILES_PER_E) __nanosleep(64);
            __syncthreads();
        }

        if (m0 < loadE) {
            const char* Aslab = (const char*)((G2 ? g_Hh : g_Xg)
                               + (size_t)e * 16 * CAP * 64);
            const char* Bslab = (const char*)((G2 ? g_w2h : g_w1h)
                               + (size_t)e * 16 * 1024 * 64);

            auto issue = [&](int c) {    // tid0 only
                const int s = c % 3;
                const uint32_t st = st0 + (uint32_t)s * STAGE_B;
                const uint32_t mb = sb + 8u * (uint32_t)s;
                const char* aS = Aslab + (((size_t)c * CAP + m0) << 7);
                const char* bS = Bslab + (((size_t)c * 1024 + n0) << 7);
                cpbulk(st,          aS,         16384, mb);
                cpbulk(st + 16384,  aS + 16384, 16384, mb);
                cpbulk(st + BH_OFF, bS,         16384, mb);
            };

            float acc[4][8][4];
#pragma unroll
            for (int i = 0; i < 4; i++)
#pragma unroll
                for (int j = 0; j < 8; j++)
#pragma unroll
                    for (int k = 0; k < 4; k++) acc[i][j][k] = 0.f;

            if (tid == 0) {
                MBARRIER_EXPECT_TX(sb + 0, TX_BYTES);
                MBARRIER_EXPECT_TX(sb + 8, TX_BYTES);
                issue(0);
                issue(1);
            }

#pragma unroll 1
            for (int c = 0; c < NCH; c++) {
                const int s = c % 3;
                MBARRIER_WAIT_PARITY(sb + 8u * (uint32_t)s, ph[s]);
                ph[s] ^= 1;
                __syncthreads();         // all readers of stage (c-1)%3 done
                if (tid == 0 && c + 2 < NCH) {
                    MBARRIER_EXPECT_TX(sb + 8u * (uint32_t)((c + 2) % 3), TX_BYTES);
                    issue(c + 2);
                }
                const uint32_t st = st0 + (uint32_t)s * STAGE_B;
                uint32_t ah[2][16], bh[2][16];
#pragma unroll
                for (int ms = 0; ms < 4; ms++)
                    ldsm4(&ah[0][4 * ms], st + abase[ms] + xqa[0]);
#pragma unroll
                for (int np = 0; np < 4; np++)
                    ldsm4(&bh[0][4 * np], st + bbase[np] + xqb[0]);
#pragma unroll
                for (int s2 = 0; s2 < 4; s2++) {
                    const int cur = s2 & 1, nxt = cur ^ 1;
                    if (s2 < 3) {
#pragma unroll
                        for (int ms = 0; ms < 4; ms++)
                            ldsm4(&ah[nxt][4 * ms], st + abase[ms] + xqa[s2 + 1]);
#pragma unroll
                        for (int np = 0; np < 4; np++)
                            ldsm4(&bh[nxt][4 * np], st + bbase[np] + xqb[s2 + 1]);
                    }
#pragma unroll
                    for (int ms = 0; ms < 4; ms++)
#pragma unroll
                        for (int ns = 0; ns < 8; ns++)
                            mma_f16(acc[ms][ns], &ah[cur][4 * ms], &bh[cur][2 * ns]);
                }
            }

            // ---- epilogue: stage in SMEM (conflict-free STS), bulk store --
            __syncthreads();             // mainloop SMEM reads finished
            const float* bE = (G2 ? b2 : b1) + e * DIM;
#pragma unroll
            for (int ms = 0; ms < 4; ms++) {
                const int rl = wm * 64 + ms * 16 + (lane >> 2);   // local row
                const int row = m0 + rl;
                float gr0 = 1.f, gr1 = 1.f;
                if (G2) {
                    gr0 = g_row_gate[e * CAP + row];
                    gr1 = g_row_gate[e * CAP + row + 8];
                }
#pragma unroll
                for (int ns = 0; ns < 8; ns++) {
                    const int col = n0 + wn * 64 + ns * 8 + 2 * (lane & 3);
                    const float2 bv = *(const float2*)(bE + col);
                    float2 v0, v1;
                    v0.x = acc[ms][ns][0] + bv.x; v0.y = acc[ms][ns][1] + bv.y;
                    v1.x = acc[ms][ns][2] + bv.x; v1.y = acc[ms][ns][3] + bv.y;
                    const uint32_t usw = ((uint32_t)(ns ^ (rl & 7)) << 4)
                                       + 4u * (lane & 3);
                    if (G2) {
                        v0.x *= gr0; v0.y *= gr0; v1.x *= gr1; v1.y *= gr1;
                        char* p = dsm + 1024 + rl * 256 + wn * 128 + usw;
                        *(uint32_t*)p = cvt2h(v0.x, v0.y);
                        *(uint32_t*)(p + 8 * 256) = cvt2h(v1.x, v1.y);
                    } else {
                        v0.x = v0.x > 0.f ? v0.x : 0.f; v0.y = v0.y > 0.f ? v0.y : 0.f;
                        v1.x = v1.x > 0.f ? v1.x : 0.f; v1.y = v1.y > 0.f ? v1.y : 0.f;
                        char* p = dsm + 1024 + wn * 32768 + rl * 128 + usw;
                        *(uint32_t*)p = cvt2h(v0.x, v0.y);
                        *(uint32_t*)(p + 8 * 128) = cvt2h(v1.x, v1.y);
                    }
                }
            }
            FENCE_PROXY_ASYNC();
            __syncthreads();
            if (tid == 0) {
                if (G2) {
                    char* o0 = (char*)g_Oh
                             + (((size_t)nt * (NE * CAP) + (size_t)e * CAP + m0) << 8);
                    bulkst(o0,         st0,         16384);
                    bulkst(o0 + 16384, st0 + 16384, 16384);
                    bulkst(o0 + 32768, st0 + 32768, 16384);
                    bulkst(o0 + 49152, st0 + 49152, 16384);
                } else {
                    const int cs = n0 >> 6;
                    char* h0 = (char*)g_Hh
                             + (((size_t)(e * 16 + cs) * CAP + m0) << 7);
                    char* h1 = (char*)g_Hh
                             + (((size_t)(e * 16 + cs + 1) * CAP + m0) << 7);
                    bulkst(h0, st0,         32768);
                    bulkst(h1, st0 + 32768, 32768);
                }
                CPB_COMMIT();
                CPB_WAIT0();
            }
        }

        __syncthreads();                 // stores issued & done before release
        if (!G2 && tid == 0) {
            __threadfence();
            atomicAdd(&g_done[e], 1);
        }
    }
}

// ---------------- combine (+stats block): out[t] = sum_k Oh[., slot_k] -----
// g_Oh layout: [nt][e*CAP+slot][2 halves x 8 units of 16B], unit ^= slot&7
__global__ void combine_kernel(float* __restrict__ out) {
    if (blockIdx.x == NTOK / 8) {
        if (threadIdx.x == 0) {
            float l[NE], s = 0.f;
#pragma unroll
            for (int e = 0; e < NE; e++) { l[e] = (float)g_load[e]; s += l[e]; }
            float inv = 1.f / (s + 1e-8f);
            float loss = 0.f;
#pragma unroll
            for (int e = 0; e < NE; e++) {
                float d = l[e] * inv;
                out[(size_t)NTOK * DIM + 1 + e] = d;
                loss -= d * logf(d + 1e-8f);
            }
            out[(size_t)NTOK * DIM] = loss;
        }
        return;
    }
    int t = blockIdx.x * 8 + (threadIdx.x >> 5);
    int lane = threadIdx.x & 31;
    float acc[4][8];
#pragma unroll
    for (int i = 0; i < 4; i++)
#pragma unroll
        for (int j = 0; j < 8; j++) acc[i][j] = 0.f;
#pragma unroll
    for (int k = 0; k < 2; k++) {
        int s = g_slot[2 * t + k];
        if (s >= 0) {
            int e = g_top[2 * t + k];
            const uint4* base = (const uint4*)g_Oh;
            const size_t rowu = ((size_t)e * CAP + s) * 16;
            const int sw = s & 7;
#pragma unroll
            for (int i = 0; i < 4; i++) {
                const int j = lane + i * 32;          // 0..127
                const int nt = j >> 4;
                const int jj = j & 15;
                const int u = ((jj & 7) ^ sw) + ((jj >> 3) << 3);
                uint4 v = __ldg(base + (size_t)nt * (NE * CAP * 16) + rowu + u);
                const uint32_t w[4] = {v.x, v.y, v.z, v.w};
#pragma unroll
                for (int jq = 0; jq < 4; jq++) {
                    float2 f = __half22float2(*(const __half2*)&w[jq]);
                    acc[i][2 * jq]     += f.x;
                    acc[i][2 * jq + 1] += f.y;
                }
            }
        }
    }
    float4* o = (float4*)(out + (size_t)t * DIM);
#pragma unroll
    for (int i = 0; i < 4; i++) {
        o[2 * (lane + i * 32)]     = make_float4(acc[i][0], acc[i][1], acc[i][2], acc[i][3]);
        o[2 * (lane + i * 32) + 1] = make_float4(acc[i][4], acc[i][5], acc[i][6], acc[i][7]);
    }
}

// ---------------- launch ----------------------------------------------------
extern "C" void kernel_launch(void* const* d_in, const int* in_sizes, int n_in,
                              void* d_out, int out_size) {
    const float* x  = (const float*)d_in[0];
    const float* Wr = (const float*)d_in[1];
    const float* br = (const float*)d_in[2];
    const float* W1 = (const float*)d_in[3];
    const float* b1 = (const float*)d_in[4];
    const float* W2 = (const float*)d_in[5];
    const float* b2 = (const float*)d_in[6];
    float* out = (float*)d_out;

    cudaFuncSetAttribute(moe_gemm_fused,
                         cudaFuncAttributeMaxDynamicSharedMemorySize, SMEM_DYN);

    void *pnext, *pdone;
    cudaGetSymbolAddress(&pnext, g_next);
    cudaGetSymbolAddress(&pdone, g_done);
    cudaMemsetAsync(pnext, 0, sizeof(int), 0);
    cudaMemsetAsync(pdone, 0, NE * sizeof(int), 0);

    cvtw_kernel<<<2 * WN4 / 256, 256>>>((const float4*)W1, (const float4*)W2);
    router_kernel<<<NTOK / 32, 256>>>(x, Wr, br);
    scan_kernel<<<NE, 1024>>>();
    gather_kernel<<<NE * CAP * 16 / 256, 256>>>();
    moe_gemm_fused<<<GRID_PERSIST, 256, SMEM_DYN>>>(b1, b2);
    combine_kernel<<<NTOK / 8 + 1, 256>>>(out);
}